// round 15
// baseline (speedup 1.0000x reference)
#include <cuda_runtime.h>
#include <math.h>
#include <stdint.h>

// Problem constants
#define B_   64
#define IN_  512
#define M_   1024
#define NG   6          // q,k,v,i,f,o
#define NSPLIT 4
#define KSL  (IN_ / NSPLIT)   // 128
#define BM   (B_ * M_)

// scratch
__device__ float g_gates[NG * B_ * M_];          // [gate][b][m]
__device__ float g_part[NSPLIT * B_ * NG * M_];  // [s][b][n_global]
__device__ unsigned int g_sem[96];               // per-column-tile arrival counters
                                                 // (zero-initialized; self-cleaning)

__device__ __forceinline__ float sigmoidf_(float v) {
    return 1.f / (1.f + __expf(-v));
}

// ---------------------------------------------------------------------------
// TF32 helpers
// ---------------------------------------------------------------------------
__device__ __forceinline__ uint32_t f2tf32(float f) {
    uint32_t u;
    asm("cvt.rna.tf32.f32 %0, %1;" : "=r"(u) : "f"(f));
    return u;
}

__device__ __forceinline__ void mma_tf32(float* c, const uint32_t* a, const uint32_t* b) {
    asm("mma.sync.aligned.m16n8k8.row.col.f32.tf32.tf32.f32 "
        "{%0,%1,%2,%3},{%4,%5,%6,%7},{%8,%9},{%0,%1,%2,%3};"
        : "+f"(c[0]), "+f"(c[1]), "+f"(c[2]), "+f"(c[3])
        : "r"(a[0]), "r"(a[1]), "r"(a[2]), "r"(a[3]),
          "r"(b[0]), "r"(b[1]));
}

// ---------------------------------------------------------------------------
// Kernel 1: split-K TF32 tensor-core GEMM with fused tail reduction.
// grid = (96, 4): bx -> 64-wide column tile, by -> 128-wide K slice.
// Each block writes raw partials; the LAST block to finish a column tile
// (per-tile counter, threadfence pattern) reduces the 4 partials from L2,
// applies bias+activation, writes g_gates, and resets the counter.
// ---------------------------------------------------------------------------
__global__ __launch_bounds__(256)
void gates_mma_sk(const float* __restrict__ x,
                  const float* __restrict__ Wq, const float* __restrict__ Wk,
                  const float* __restrict__ Wv, const float* __restrict__ Wi,
                  const float* __restrict__ Wf, const float* __restrict__ Wo,
                  const float* __restrict__ bq, const float* __restrict__ bk,
                  const float* __restrict__ bv, const float* __restrict__ bi,
                  const float* __restrict__ bf, const float* __restrict__ bo)
{
    const int n_global0 = blockIdx.x * 64;
    const int gate      = n_global0 >> 10;
    const int n_local0  = n_global0 & (M_ - 1);
    const int s         = blockIdx.y;
    const int k_base    = s * KSL;

    const float* W; const float* bias;
    switch (gate) {
        case 0: W = Wq; bias = bq; break;
        case 1: W = Wk; bias = bk; break;
        case 2: W = Wv; bias = bv; break;
        case 3: W = Wi; bias = bi; break;
        case 4: W = Wf; bias = bf; break;
        default: W = Wo; bias = bo; break;
    }

    __shared__ uint32_t Xs[2][64][36];
    __shared__ uint32_t Ws[2][64][36];
    __shared__ unsigned int s_old;

    const int tid  = threadIdx.x;
    const int wid  = tid >> 5;
    const int lane = tid & 31;
    const int g    = lane >> 2;
    const int tig  = lane & 3;
    const int warp_m = wid & 1;
    const int warp_n = wid >> 1;

    const int lrow0 = tid >> 3;
    const int lrow1 = lrow0 + 32;
    const int lcol  = (tid & 7) * 4;

    const float* xg0 = x + lrow0 * IN_ + k_base + lcol;
    const float* xg1 = x + lrow1 * IN_ + k_base + lcol;
    const float* wg0 = W + (n_local0 + lrow0) * IN_ + k_base + lcol;
    const float* wg1 = W + (n_local0 + lrow1) * IN_ + k_base + lcol;

    float acc[2][2][4];
    #pragma unroll
    for (int mt = 0; mt < 2; mt++)
        #pragma unroll
        for (int nt = 0; nt < 2; nt++)
            #pragma unroll
            for (int e = 0; e < 4; e++) acc[mt][nt][e] = 0.f;

    float4 xr0, xr1, wr0, wr1;
    xr0 = *(const float4*)xg0;
    xr1 = *(const float4*)xg1;
    wr0 = *(const float4*)wg0;
    wr1 = *(const float4*)wg1;

    {
        uint4 u;
        u.x = f2tf32(xr0.x); u.y = f2tf32(xr0.y); u.z = f2tf32(xr0.z); u.w = f2tf32(xr0.w);
        *(uint4*)&Xs[0][lrow0][lcol] = u;
        u.x = f2tf32(xr1.x); u.y = f2tf32(xr1.y); u.z = f2tf32(xr1.z); u.w = f2tf32(xr1.w);
        *(uint4*)&Xs[0][lrow1][lcol] = u;
        u.x = f2tf32(wr0.x); u.y = f2tf32(wr0.y); u.z = f2tf32(wr0.z); u.w = f2tf32(wr0.w);
        *(uint4*)&Ws[0][lrow0][lcol] = u;
        u.x = f2tf32(wr1.x); u.y = f2tf32(wr1.y); u.z = f2tf32(wr1.z); u.w = f2tf32(wr1.w);
        *(uint4*)&Ws[0][lrow1][lcol] = u;
    }
    __syncthreads();

    int buf = 0;
    #pragma unroll 1
    for (int it = 0; it < KSL / 32; it++) {
        if (it < KSL / 32 - 1) {
            const int k0 = (it + 1) * 32;
            xr0 = *(const float4*)(xg0 + k0);
            xr1 = *(const float4*)(xg1 + k0);
            wr0 = *(const float4*)(wg0 + k0);
            wr1 = *(const float4*)(wg1 + k0);
        }

        #pragma unroll
        for (int ks = 0; ks < 4; ks++) {
            const int ko = ks * 8;
            uint32_t af[2][4];
            #pragma unroll
            for (int mt = 0; mt < 2; mt++) {
                const int r = warp_m * 32 + mt * 16 + g;
                af[mt][0] = Xs[buf][r][ko + tig];
                af[mt][1] = Xs[buf][r + 8][ko + tig];
                af[mt][2] = Xs[buf][r][ko + tig + 4];
                af[mt][3] = Xs[buf][r + 8][ko + tig + 4];
            }
            uint32_t bfr[2][2];
            #pragma unroll
            for (int nt = 0; nt < 2; nt++) {
                const int c = warp_n * 16 + nt * 8 + g;
                bfr[nt][0] = Ws[buf][c][ko + tig];
                bfr[nt][1] = Ws[buf][c][ko + tig + 4];
            }
            #pragma unroll
            for (int mt = 0; mt < 2; mt++)
                #pragma unroll
                for (int nt = 0; nt < 2; nt++)
                    mma_tf32(acc[mt][nt], af[mt], bfr[nt]);
        }

        if (it < KSL / 32 - 1) {
            const int nb = buf ^ 1;
            uint4 u;
            u.x = f2tf32(xr0.x); u.y = f2tf32(xr0.y); u.z = f2tf32(xr0.z); u.w = f2tf32(xr0.w);
            *(uint4*)&Xs[nb][lrow0][lcol] = u;
            u.x = f2tf32(xr1.x); u.y = f2tf32(xr1.y); u.z = f2tf32(xr1.z); u.w = f2tf32(xr1.w);
            *(uint4*)&Xs[nb][lrow1][lcol] = u;
            u.x = f2tf32(wr0.x); u.y = f2tf32(wr0.y); u.z = f2tf32(wr0.z); u.w = f2tf32(wr0.w);
            *(uint4*)&Ws[nb][lrow0][lcol] = u;
            u.x = f2tf32(wr1.x); u.y = f2tf32(wr1.y); u.z = f2tf32(wr1.z); u.w = f2tf32(wr1.w);
            *(uint4*)&Ws[nb][lrow1][lcol] = u;
            __syncthreads();
            buf = nb;
        }
    }

    // write raw partials (L2-resident)
    float* outp = g_part + (size_t)s * ((size_t)B_ * NG * M_);
    #pragma unroll
    for (int mt = 0; mt < 2; mt++) {
        const int r0 = warp_m * 32 + mt * 16 + g;
        #pragma unroll
        for (int nt = 0; nt < 2; nt++) {
            const int ncol = n_global0 + warp_n * 16 + nt * 8 + 2 * tig;
            *(float2*)&outp[(size_t)r0 * (NG * M_) + ncol] =
                make_float2(acc[mt][nt][0], acc[mt][nt][1]);
            *(float2*)&outp[(size_t)(r0 + 8) * (NG * M_) + ncol] =
                make_float2(acc[mt][nt][2], acc[mt][nt][3]);
        }
    }

    // --- tail reduction: last block per column tile sums the 4 partials ---
    __threadfence();            // make this block's partials globally visible
    __syncthreads();
    if (tid == 0) s_old = atomicAdd(&g_sem[blockIdx.x], 1u);
    __syncthreads();
    if (s_old != NSPLIT - 1) return;

    __threadfence();            // acquire: other blocks' partials now visible

    // 64 batches x 16 float4-cols = 1024 items, 4 per thread
    #pragma unroll
    for (int i = tid; i < 1024; i += 256) {
        const int b    = i >> 4;
        const int c4   = i & 15;
        const int ncol = n_global0 + c4 * 4;
        const float* base = g_part + (size_t)b * (NG * M_) + ncol;
        float4 a = *(const float4*)base;
        #pragma unroll
        for (int ss = 1; ss < NSPLIT; ss++) {
            float4 p = *(const float4*)(base + (size_t)ss * ((size_t)B_ * NG * M_));
            a.x += p.x; a.y += p.y; a.z += p.z; a.w += p.w;
        }
        const int nl = n_local0 + c4 * 4;
        const float4 bv4 = *(const float4*)&bias[nl];
        a.x += bv4.x; a.y += bv4.y; a.z += bv4.z; a.w += bv4.w;

        if (gate == 1) {
            a.x *= 0.03125f; a.y *= 0.03125f; a.z *= 0.03125f; a.w *= 0.03125f;
        } else if (gate == 3) {
            a.x = __expf(a.x); a.y = __expf(a.y);
            a.z = __expf(a.z); a.w = __expf(a.w);
        } else if (gate >= 4) {
            a.x = sigmoidf_(a.x);
            a.y = sigmoidf_(a.y);
            a.z = sigmoidf_(a.z);
            a.w = sigmoidf_(a.w);
        }
        *(float4*)&g_gates[(size_t)gate * BM + b * M_ + nl] = a;
    }

    if (tid == 0) atomicExch(&g_sem[blockIdx.x], 0u);   // self-clean for next replay
}

// ---------------------------------------------------------------------------
// Kernel 2 (R10/R7 version, measured 82.2us — frozen):
// C_t update + h_tilde + n_t + denom + h_t. grid = (16, 64).
// ---------------------------------------------------------------------------
__global__ __launch_bounds__(256)
void update_C(const float* __restrict__ Cprev, const float* __restrict__ nprev,
              float* __restrict__ Cout, float* __restrict__ out_h,
              float* __restrict__ out_n)
{
    const int b = blockIdx.y;
    __shared__ float sk[M_];
    __shared__ float sq[M_];
    __shared__ float red[8];
    __shared__ float s_inv;

    const float* gq = g_gates + 0 * BM + b * M_;
    const float* gk = g_gates + 1 * BM + b * M_;
    ((float4*)sk)[threadIdx.x] = ((const float4*)gk)[threadIdx.x];
    ((float4*)sq)[threadIdx.x] = ((const float4*)gq)[threadIdx.x];

    const int warp = threadIdx.x >> 5;
    const int lane = threadIdx.x & 31;
    const float* gv = g_gates + 2 * BM + b * M_;
    const float* gi = g_gates + 3 * BM + b * M_;
    const float* gf = g_gates + 4 * BM + b * M_;
    const float* go = g_gates + 5 * BM + b * M_;

    __syncthreads();

    // --- denom prologue: n_t = f*n_prev + i*k ; part = n_t . q ---
    {
        const int t = threadIdx.x;
        float4 f4 = ((const float4*)gf)[t];
        float4 i4 = ((const float4*)gi)[t];
        float4 p4 = ((const float4*)(nprev + b * M_))[t];
        float4 k4 = ((const float4*)sk)[t];
        float4 q4 = ((const float4*)sq)[t];
        float4 n4;
        n4.x = fmaf(f4.x, p4.x, i4.x * k4.x);
        n4.y = fmaf(f4.y, p4.y, i4.y * k4.y);
        n4.z = fmaf(f4.z, p4.z, i4.z * k4.z);
        n4.w = fmaf(f4.w, p4.w, i4.w * k4.w);
        if (blockIdx.x == 0)
            ((float4*)(out_n + b * M_))[t] = n4;
        float part = n4.x * q4.x + n4.y * q4.y + n4.z * q4.z + n4.w * q4.w;
        #pragma unroll
        for (int off = 16; off; off >>= 1)
            part += __shfl_xor_sync(0xffffffffu, part, off);
        if (lane == 0) red[warp] = part;
        __syncthreads();
        if (threadIdx.x == 0) {
            float d = red[0] + red[1] + red[2] + red[3]
                    + red[4] + red[5] + red[6] + red[7];
            s_inv = 1.0f / fmaxf(d, 1.0f);
        }
        __syncthreads();
    }
    const float inv = s_inv;

    const float4* sk4 = (const float4*)sk;
    const float4* sq4 = (const float4*)sq;

    const int m_base = blockIdx.x * 64 + warp;

    float4 cur[8], nxt[8];
    int m = m_base;
    float fm = gf[m];
    float cm = gi[m] * gv[m];
    {
        const float4* cp = (const float4*)(Cprev + ((size_t)b * M_ + m) * M_);
        #pragma unroll
        for (int j = 0; j < 8; j++) cur[j] = __ldcs(cp + j * 32 + lane);
    }

    #pragma unroll
    for (int r = 0; r < 8; r++) {
        float fmn = 0.f, cmn = 0.f;
        if (r < 7) {
            const int mn = m_base + (r + 1) * 8;
            fmn = gf[mn];
            cmn = gi[mn] * gv[mn];
            const float4* cpn = (const float4*)(Cprev + ((size_t)b * M_ + mn) * M_);
            #pragma unroll
            for (int j = 0; j < 8; j++) nxt[j] = __ldcs(cpn + j * 32 + lane);
        }

        float4* co = (float4*)(Cout + ((size_t)b * M_ + m) * M_);
        float dot0 = 0.f, dot1 = 0.f;
        #pragma unroll
        for (int j = 0; j < 8; j++) {
            const int n4 = j * 32 + lane;
            float4 kk = sk4[n4];
            float4 qq = sq4[n4];
            float4 o;
            o.x = fmaf(fm, cur[j].x, cm * kk.x);
            o.y = fmaf(fm, cur[j].y, cm * kk.y);
            o.z = fmaf(fm, cur[j].z, cm * kk.z);
            o.w = fmaf(fm, cur[j].w, cm * kk.w);
            __stcs(co + n4, o);
            if (j & 1) {
                dot1 = fmaf(o.x, qq.x, dot1);
                dot1 = fmaf(o.y, qq.y, dot1);
                dot1 = fmaf(o.z, qq.z, dot1);
                dot1 = fmaf(o.w, qq.w, dot1);
            } else {
                dot0 = fmaf(o.x, qq.x, dot0);
                dot0 = fmaf(o.y, qq.y, dot0);
                dot0 = fmaf(o.z, qq.z, dot0);
                dot0 = fmaf(o.w, qq.w, dot0);
            }
        }
        float dot = dot0 + dot1;
        #pragma unroll
        for (int off = 16; off; off >>= 1)
            dot += __shfl_xor_sync(0xffffffffu, dot, off);
        if (lane == 0)
            out_h[b * M_ + m] = go[m] * dot * inv;

        m = m_base + (r + 1) * 8;
        fm = fmn;
        cm = cmn;
        #pragma unroll
        for (int j = 0; j < 8; j++) cur[j] = nxt[j];
    }
}

// ---------------------------------------------------------------------------
// Launch. Inputs (metadata order):
// 0 x, 1 h_prev, 2 c_prev, 3 C_prev, 4 n_prev, 5 m_prev,
// 6 Wq, 7 bq, 8 Wk, 9 bk, 10 Wv, 11 bv, 12 Wi, 13 bi, 14 Wf, 15 bf, 16 Wo, 17 bo
// Output: concat(h_t [64*1024], C_t [64*1024*1024], n_t [64*1024])
// ---------------------------------------------------------------------------
extern "C" void kernel_launch(void* const* d_in, const int* in_sizes, int n_in,
                              void* d_out, int out_size)
{
    const float* x     = (const float*)d_in[0];
    const float* Cprev = (const float*)d_in[3];
    const float* nprev = (const float*)d_in[4];

    const float* Wq = (const float*)d_in[6];  const float* bq = (const float*)d_in[7];
    const float* Wk = (const float*)d_in[8];  const float* bk = (const float*)d_in[9];
    const float* Wv = (const float*)d_in[10]; const float* bv = (const float*)d_in[11];
    const float* Wi = (const float*)d_in[12]; const float* bi = (const float*)d_in[13];
    const float* Wf = (const float*)d_in[14]; const float* bf = (const float*)d_in[15];
    const float* Wo = (const float*)d_in[16]; const float* bo = (const float*)d_in[17];

    float* out   = (float*)d_out;
    float* out_h = out;                                    // [64*1024]
    float* out_C = out + (size_t)B_ * M_;                  // [64*1024*1024]
    float* out_n = out + (size_t)B_ * M_ + (size_t)B_ * M_ * M_;

    dim3 grid1(96, NSPLIT);
    gates_mma_sk<<<grid1, 256>>>(x, Wq, Wk, Wv, Wi, Wf, Wo,
                                 bq, bk, bv, bi, bf, bo);

    dim3 grid2(16, 64);
    update_C<<<grid2, 256>>>(Cprev, nprev, out_C, out_h, out_n);
}

// round 16
// speedup vs baseline: 1.0062x; 1.0062x over previous
#include <cuda_runtime.h>
#include <math.h>
#include <stdint.h>

// Problem constants
#define B_   64
#define IN_  512
#define M_   1024
#define NG   6          // q,k,v,i,f,o
#define NSPLIT 4
#define KSL  (IN_ / NSPLIT)   // 128
#define BM   (B_ * M_)

// scratch
__device__ float g_gates[NG * B_ * M_];          // [gate][b][m]
__device__ float g_part[NSPLIT * B_ * NG * M_];  // [s][b][n_global]

__device__ __forceinline__ float sigmoidf_(float v) {
    return 1.f / (1.f + __expf(-v));
}

// ---------------------------------------------------------------------------
// TF32 helpers
// ---------------------------------------------------------------------------
__device__ __forceinline__ uint32_t f2tf32(float f) {
    uint32_t u;
    asm("cvt.rna.tf32.f32 %0, %1;" : "=r"(u) : "f"(f));
    return u;
}

__device__ __forceinline__ void mma_tf32(float* c, const uint32_t* a, const uint32_t* b) {
    asm("mma.sync.aligned.m16n8k8.row.col.f32.tf32.tf32.f32 "
        "{%0,%1,%2,%3},{%4,%5,%6,%7},{%8,%9},{%0,%1,%2,%3};"
        : "+f"(c[0]), "+f"(c[1]), "+f"(c[2]), "+f"(c[3])
        : "r"(a[0]), "r"(a[1]), "r"(a[2]), "r"(a[3]),
          "r"(b[0]), "r"(b[1]));
}

// ---------------------------------------------------------------------------
// Kernel 1a: split-K TF32 tensor-core GEMM partials (R10 version, 10.6us)
// grid = (96, 4). Block tile 64x64x32 double-buffered, warp grid 2m x 4n.
// ---------------------------------------------------------------------------
__global__ __launch_bounds__(256)
void gates_mma_sk(const float* __restrict__ x,
                  const float* __restrict__ Wq, const float* __restrict__ Wk,
                  const float* __restrict__ Wv, const float* __restrict__ Wi,
                  const float* __restrict__ Wf, const float* __restrict__ Wo)
{
    const int n_global0 = blockIdx.x * 64;
    const int gate      = n_global0 >> 10;
    const int n_local0  = n_global0 & (M_ - 1);
    const int s         = blockIdx.y;
    const int k_base    = s * KSL;

    const float* W;
    switch (gate) {
        case 0: W = Wq; break;
        case 1: W = Wk; break;
        case 2: W = Wv; break;
        case 3: W = Wi; break;
        case 4: W = Wf; break;
        default: W = Wo; break;
    }

    __shared__ uint32_t Xs[2][64][36];
    __shared__ uint32_t Ws[2][64][36];

    const int tid  = threadIdx.x;
    const int wid  = tid >> 5;
    const int lane = tid & 31;
    const int g    = lane >> 2;
    const int tig  = lane & 3;
    const int warp_m = wid & 1;
    const int warp_n = wid >> 1;

    const int lrow0 = tid >> 3;
    const int lrow1 = lrow0 + 32;
    const int lcol  = (tid & 7) * 4;

    const float* xg0 = x + lrow0 * IN_ + k_base + lcol;
    const float* xg1 = x + lrow1 * IN_ + k_base + lcol;
    const float* wg0 = W + (n_local0 + lrow0) * IN_ + k_base + lcol;
    const float* wg1 = W + (n_local0 + lrow1) * IN_ + k_base + lcol;

    float acc[2][2][4];
    #pragma unroll
    for (int mt = 0; mt < 2; mt++)
        #pragma unroll
        for (int nt = 0; nt < 2; nt++)
            #pragma unroll
            for (int e = 0; e < 4; e++) acc[mt][nt][e] = 0.f;

    float4 xr0, xr1, wr0, wr1;
    xr0 = *(const float4*)xg0;
    xr1 = *(const float4*)xg1;
    wr0 = *(const float4*)wg0;
    wr1 = *(const float4*)wg1;

    {
        uint4 u;
        u.x = f2tf32(xr0.x); u.y = f2tf32(xr0.y); u.z = f2tf32(xr0.z); u.w = f2tf32(xr0.w);
        *(uint4*)&Xs[0][lrow0][lcol] = u;
        u.x = f2tf32(xr1.x); u.y = f2tf32(xr1.y); u.z = f2tf32(xr1.z); u.w = f2tf32(xr1.w);
        *(uint4*)&Xs[0][lrow1][lcol] = u;
        u.x = f2tf32(wr0.x); u.y = f2tf32(wr0.y); u.z = f2tf32(wr0.z); u.w = f2tf32(wr0.w);
        *(uint4*)&Ws[0][lrow0][lcol] = u;
        u.x = f2tf32(wr1.x); u.y = f2tf32(wr1.y); u.z = f2tf32(wr1.z); u.w = f2tf32(wr1.w);
        *(uint4*)&Ws[0][lrow1][lcol] = u;
    }
    __syncthreads();

    int buf = 0;
    #pragma unroll 1
    for (int it = 0; it < KSL / 32; it++) {
        if (it < KSL / 32 - 1) {
            const int k0 = (it + 1) * 32;
            xr0 = *(const float4*)(xg0 + k0);
            xr1 = *(const float4*)(xg1 + k0);
            wr0 = *(const float4*)(wg0 + k0);
            wr1 = *(const float4*)(wg1 + k0);
        }

        #pragma unroll
        for (int ks = 0; ks < 4; ks++) {
            const int ko = ks * 8;
            uint32_t af[2][4];
            #pragma unroll
            for (int mt = 0; mt < 2; mt++) {
                const int r = warp_m * 32 + mt * 16 + g;
                af[mt][0] = Xs[buf][r][ko + tig];
                af[mt][1] = Xs[buf][r + 8][ko + tig];
                af[mt][2] = Xs[buf][r][ko + tig + 4];
                af[mt][3] = Xs[buf][r + 8][ko + tig + 4];
            }
            uint32_t bfr[2][2];
            #pragma unroll
            for (int nt = 0; nt < 2; nt++) {
                const int c = warp_n * 16 + nt * 8 + g;
                bfr[nt][0] = Ws[buf][c][ko + tig];
                bfr[nt][1] = Ws[buf][c][ko + tig + 4];
            }
            #pragma unroll
            for (int mt = 0; mt < 2; mt++)
                #pragma unroll
                for (int nt = 0; nt < 2; nt++)
                    mma_tf32(acc[mt][nt], af[mt], bfr[nt]);
        }

        if (it < KSL / 32 - 1) {
            const int nb = buf ^ 1;
            uint4 u;
            u.x = f2tf32(xr0.x); u.y = f2tf32(xr0.y); u.z = f2tf32(xr0.z); u.w = f2tf32(xr0.w);
            *(uint4*)&Xs[nb][lrow0][lcol] = u;
            u.x = f2tf32(xr1.x); u.y = f2tf32(xr1.y); u.z = f2tf32(xr1.z); u.w = f2tf32(xr1.w);
            *(uint4*)&Xs[nb][lrow1][lcol] = u;
            u.x = f2tf32(wr0.x); u.y = f2tf32(wr0.y); u.z = f2tf32(wr0.z); u.w = f2tf32(wr0.w);
            *(uint4*)&Ws[nb][lrow0][lcol] = u;
            u.x = f2tf32(wr1.x); u.y = f2tf32(wr1.y); u.z = f2tf32(wr1.z); u.w = f2tf32(wr1.w);
            *(uint4*)&Ws[nb][lrow1][lcol] = u;
            __syncthreads();
            buf = nb;
        }
    }

    float* outp = g_part + (size_t)s * ((size_t)B_ * NG * M_);
    #pragma unroll
    for (int mt = 0; mt < 2; mt++) {
        const int r0 = warp_m * 32 + mt * 16 + g;
        #pragma unroll
        for (int nt = 0; nt < 2; nt++) {
            const int ncol = n_global0 + warp_n * 16 + nt * 8 + 2 * tig;
            *(float2*)&outp[(size_t)r0 * (NG * M_) + ncol] =
                make_float2(acc[mt][nt][0], acc[mt][nt][1]);
            *(float2*)&outp[(size_t)(r0 + 8) * (NG * M_) + ncol] =
                make_float2(acc[mt][nt][2], acc[mt][nt][3]);
        }
    }
}

// ---------------------------------------------------------------------------
// Kernel 1b: reduce partials + bias + activation -> g_gates[gate][b][m]
// 192 blocks, 2 float4 per thread -> 8 independent loads in flight (MLP=8).
// ---------------------------------------------------------------------------
__global__ __launch_bounds__(256)
void gates_reduce(const float* __restrict__ bq, const float* __restrict__ bk,
                  const float* __restrict__ bv, const float* __restrict__ bi,
                  const float* __restrict__ bf, const float* __restrict__ bo)
{
    #pragma unroll
    for (int rep = 0; rep < 2; rep++) {
        const int idx = (blockIdx.x * 2 + rep) * 256 + threadIdx.x;  // [0, 98304)
        const int b   = idx / (NG * M_ / 4);
        const int c4  = idx % (NG * M_ / 4);
        const int n   = c4 * 4;
        const int gate = n >> 10;
        const int nl   = n & (M_ - 1);

        const float* bias;
        switch (gate) {
            case 0: bias = bq; break;
            case 1: bias = bk; break;
            case 2: bias = bv; break;
            case 3: bias = bi; break;
            case 4: bias = bf; break;
            default: bias = bo; break;
        }

        float4 acc = *(const float4*)&g_part[((size_t)0 * B_ + b) * (NG * M_) + n];
        #pragma unroll
        for (int s = 1; s < NSPLIT; s++) {
            float4 p = *(const float4*)&g_part[((size_t)s * B_ + b) * (NG * M_) + n];
            acc.x += p.x; acc.y += p.y; acc.z += p.z; acc.w += p.w;
        }
        const float4 bv4 = *(const float4*)&bias[nl];
        acc.x += bv4.x; acc.y += bv4.y; acc.z += bv4.z; acc.w += bv4.w;

        if (gate == 1) {
            acc.x *= 0.03125f; acc.y *= 0.03125f; acc.z *= 0.03125f; acc.w *= 0.03125f;
        } else if (gate == 3) {
            acc.x = __expf(acc.x); acc.y = __expf(acc.y);
            acc.z = __expf(acc.z); acc.w = __expf(acc.w);
        } else if (gate >= 4) {
            acc.x = sigmoidf_(acc.x);
            acc.y = sigmoidf_(acc.y);
            acc.z = sigmoidf_(acc.z);
            acc.w = sigmoidf_(acc.w);
        }
        *(float4*)&g_gates[(size_t)gate * BM + b * M_ + nl] = acc;
    }
}

// ---------------------------------------------------------------------------
// Kernel 2: C_t update + h_tilde + n_t + denom + h_t. grid = (16, 64).
// R7/R10 pipelined structure with ONE change: the per-row dot uses C_prev
// (h_tilde = fm*(C_prev.q) + cm*(k.q)) so the dot chain no longer depends on
// the computed o — better ILP; (k.q) is reduced once in the prologue.
// ---------------------------------------------------------------------------
__global__ __launch_bounds__(256)
void update_C(const float* __restrict__ Cprev, const float* __restrict__ nprev,
              float* __restrict__ Cout, float* __restrict__ out_h,
              float* __restrict__ out_n)
{
    const int b = blockIdx.y;
    __shared__ float sk[M_];
    __shared__ float sq[M_];
    __shared__ float red[8], red2[8];
    __shared__ float s_inv, s_kq;

    const float* gq = g_gates + 0 * BM + b * M_;
    const float* gk = g_gates + 1 * BM + b * M_;
    ((float4*)sk)[threadIdx.x] = ((const float4*)gk)[threadIdx.x];
    ((float4*)sq)[threadIdx.x] = ((const float4*)gq)[threadIdx.x];

    const int warp = threadIdx.x >> 5;
    const int lane = threadIdx.x & 31;
    const float* gv = g_gates + 2 * BM + b * M_;
    const float* gi = g_gates + 3 * BM + b * M_;
    const float* gf = g_gates + 4 * BM + b * M_;
    const float* go = g_gates + 5 * BM + b * M_;

    __syncthreads();

    // --- prologue: n_t = f*n_prev + i*k ; denom = n_t.q ; kq = k.q ---
    {
        const int t = threadIdx.x;
        float4 f4 = ((const float4*)gf)[t];
        float4 i4 = ((const float4*)gi)[t];
        float4 p4 = ((const float4*)(nprev + b * M_))[t];
        float4 k4 = ((const float4*)sk)[t];
        float4 q4 = ((const float4*)sq)[t];
        float4 n4;
        n4.x = fmaf(f4.x, p4.x, i4.x * k4.x);
        n4.y = fmaf(f4.y, p4.y, i4.y * k4.y);
        n4.z = fmaf(f4.z, p4.z, i4.z * k4.z);
        n4.w = fmaf(f4.w, p4.w, i4.w * k4.w);
        if (blockIdx.x == 0)
            ((float4*)(out_n + b * M_))[t] = n4;
        float part = n4.x * q4.x + n4.y * q4.y + n4.z * q4.z + n4.w * q4.w;
        float pkq  = k4.x * q4.x + k4.y * q4.y + k4.z * q4.z + k4.w * q4.w;
        #pragma unroll
        for (int off = 16; off; off >>= 1) {
            part += __shfl_xor_sync(0xffffffffu, part, off);
            pkq  += __shfl_xor_sync(0xffffffffu, pkq,  off);
        }
        if (lane == 0) { red[warp] = part; red2[warp] = pkq; }
        __syncthreads();
        if (threadIdx.x == 0) {
            float d = red[0] + red[1] + red[2] + red[3]
                    + red[4] + red[5] + red[6] + red[7];
            s_inv = 1.0f / fmaxf(d, 1.0f);
            s_kq  = red2[0] + red2[1] + red2[2] + red2[3]
                  + red2[4] + red2[5] + red2[6] + red2[7];
        }
        __syncthreads();
    }
    const float inv = s_inv;
    const float kq  = s_kq;

    const float4* sk4 = (const float4*)sk;
    const float4* sq4 = (const float4*)sq;

    const int m_base = blockIdx.x * 64 + warp;

    float4 cur[8], nxt[8];
    int m = m_base;
    float fm = gf[m];
    float cm = gi[m] * gv[m];
    {
        const float4* cp = (const float4*)(Cprev + ((size_t)b * M_ + m) * M_);
        #pragma unroll
        for (int j = 0; j < 8; j++) cur[j] = __ldcs(cp + j * 32 + lane);
    }

    #pragma unroll
    for (int r = 0; r < 8; r++) {
        float fmn = 0.f, cmn = 0.f;
        if (r < 7) {
            const int mn = m_base + (r + 1) * 8;
            fmn = gf[mn];
            cmn = gi[mn] * gv[mn];
            const float4* cpn = (const float4*)(Cprev + ((size_t)b * M_ + mn) * M_);
            #pragma unroll
            for (int j = 0; j < 8; j++) nxt[j] = __ldcs(cpn + j * 32 + lane);
        }

        float4* co = (float4*)(Cout + ((size_t)b * M_ + m) * M_);
        float dot0 = 0.f, dot1 = 0.f;          // dot of C_prev row with q
        #pragma unroll
        for (int j = 0; j < 8; j++) {
            const int n4 = j * 32 + lane;
            float4 kk = sk4[n4];
            float4 qq = sq4[n4];
            float4 o;
            o.x = fmaf(fm, cur[j].x, cm * kk.x);
            o.y = fmaf(fm, cur[j].y, cm * kk.y);
            o.z = fmaf(fm, cur[j].z, cm * kk.z);
            o.w = fmaf(fm, cur[j].w, cm * kk.w);
            __stcs(co + n4, o);
            if (j & 1) {
                dot1 = fmaf(cur[j].x, qq.x, dot1);
                dot1 = fmaf(cur[j].y, qq.y, dot1);
                dot1 = fmaf(cur[j].z, qq.z, dot1);
                dot1 = fmaf(cur[j].w, qq.w, dot1);
            } else {
                dot0 = fmaf(cur[j].x, qq.x, dot0);
                dot0 = fmaf(cur[j].y, qq.y, dot0);
                dot0 = fmaf(cur[j].z, qq.z, dot0);
                dot0 = fmaf(cur[j].w, qq.w, dot0);
            }
        }
        float dot = dot0 + dot1;
        #pragma unroll
        for (int off = 16; off; off >>= 1)
            dot += __shfl_xor_sync(0xffffffffu, dot, off);
        if (lane == 0) {
            const float htil = fmaf(fm, dot, cm * kq);
            out_h[b * M_ + m] = go[m] * htil * inv;
        }

        m = m_base + (r + 1) * 8;
        fm = fmn;
        cm = cmn;
        #pragma unroll
        for (int j = 0; j < 8; j++) cur[j] = nxt[j];
    }
}

// ---------------------------------------------------------------------------
// Launch. Inputs (metadata order):
// 0 x, 1 h_prev, 2 c_prev, 3 C_prev, 4 n_prev, 5 m_prev,
// 6 Wq, 7 bq, 8 Wk, 9 bk, 10 Wv, 11 bv, 12 Wi, 13 bi, 14 Wf, 15 bf, 16 Wo, 17 bo
// Output: concat(h_t [64*1024], C_t [64*1024*1024], n_t [64*1024])
// ---------------------------------------------------------------------------
extern "C" void kernel_launch(void* const* d_in, const int* in_sizes, int n_in,
                              void* d_out, int out_size)
{
    const float* x     = (const float*)d_in[0];
    const float* Cprev = (const float*)d_in[3];
    const float* nprev = (const float*)d_in[4];

    const float* Wq = (const float*)d_in[6];  const float* bq = (const float*)d_in[7];
    const float* Wk = (const float*)d_in[8];  const float* bk = (const float*)d_in[9];
    const float* Wv = (const float*)d_in[10]; const float* bv = (const float*)d_in[11];
    const float* Wi = (const float*)d_in[12]; const float* bi = (const float*)d_in[13];
    const float* Wf = (const float*)d_in[14]; const float* bf = (const float*)d_in[15];
    const float* Wo = (const float*)d_in[16]; const float* bo = (const float*)d_in[17];

    float* out   = (float*)d_out;
    float* out_h = out;                                    // [64*1024]
    float* out_C = out + (size_t)B_ * M_;                  // [64*1024*1024]
    float* out_n = out + (size_t)B_ * M_ + (size_t)B_ * M_ * M_;

    dim3 grid1(96, NSPLIT);
    gates_mma_sk<<<grid1, 256>>>(x, Wq, Wk, Wv, Wi, Wf, Wo);

    gates_reduce<<<192, 256>>>(bq, bk, bv, bi, bf, bo);

    dim3 grid2(16, 64);
    update_C<<<grid2, 256>>>(Cprev, nprev, out_C, out_h, out_n);
}

// round 17
// speedup vs baseline: 1.0252x; 1.0189x over previous
#include <cuda_runtime.h>
#include <math.h>
#include <stdint.h>

// Problem constants
#define B_   64
#define IN_  512
#define M_   1024
#define NG   6          // q,k,v,i,f,o
#define NSPLIT 4
#define KSL  (IN_ / NSPLIT)   // 128

// scratch
__device__ float g_gates[NG * B_ * M_];          // [gate][b][m]
__device__ float g_part[NSPLIT * B_ * NG * M_];  // [s][b][n_global]

// ---------------------------------------------------------------------------
// TF32 helpers
// ---------------------------------------------------------------------------
__device__ __forceinline__ uint32_t f2tf32(float f) {
    uint32_t u;
    asm("cvt.rna.tf32.f32 %0, %1;" : "=r"(u) : "f"(f));
    return u;
}

__device__ __forceinline__ void mma_tf32(float* c, const uint32_t* a, const uint32_t* b) {
    asm("mma.sync.aligned.m16n8k8.row.col.f32.tf32.tf32.f32 "
        "{%0,%1,%2,%3},{%4,%5,%6,%7},{%8,%9},{%0,%1,%2,%3};"
        : "+f"(c[0]), "+f"(c[1]), "+f"(c[2]), "+f"(c[3])
        : "r"(a[0]), "r"(a[1]), "r"(a[2]), "r"(a[3]),
          "r"(b[0]), "r"(b[1]));
}

// ---------------------------------------------------------------------------
// Kernel 1a: split-K TF32 tensor-core GEMM partials. (measured 10.4-10.6us)
// grid = (96, 4). Block tile 64x64x32 double-buffered, warp grid 2m x 4n.
// ---------------------------------------------------------------------------
__global__ __launch_bounds__(256)
void gates_mma_sk(const float* __restrict__ x,
                  const float* __restrict__ Wq, const float* __restrict__ Wk,
                  const float* __restrict__ Wv, const float* __restrict__ Wi,
                  const float* __restrict__ Wf, const float* __restrict__ Wo)
{
    const int n_global0 = blockIdx.x * 64;          // [0, 6144)
    const int gate      = n_global0 >> 10;
    const int n_local0  = n_global0 & (M_ - 1);
    const int s         = blockIdx.y;
    const int k_base    = s * KSL;

    const float* W;
    switch (gate) {
        case 0: W = Wq; break;
        case 1: W = Wk; break;
        case 2: W = Wv; break;
        case 3: W = Wi; break;
        case 4: W = Wf; break;
        default: W = Wo; break;
    }

    __shared__ uint32_t Xs[2][64][36];   // [buf][b][k] tf32 bits
    __shared__ uint32_t Ws[2][64][36];   // [buf][n][k] tf32 bits

    const int tid  = threadIdx.x;
    const int wid  = tid >> 5;
    const int lane = tid & 31;
    const int g    = lane >> 2;
    const int tig  = lane & 3;
    const int warp_m = wid & 1;
    const int warp_n = wid >> 1;

    const int lrow0 = tid >> 3;
    const int lrow1 = lrow0 + 32;
    const int lcol  = (tid & 7) * 4;

    const float* xg0 = x + lrow0 * IN_ + k_base + lcol;
    const float* xg1 = x + lrow1 * IN_ + k_base + lcol;
    const float* wg0 = W + (n_local0 + lrow0) * IN_ + k_base + lcol;
    const float* wg1 = W + (n_local0 + lrow1) * IN_ + k_base + lcol;

    float acc[2][2][4];
    #pragma unroll
    for (int mt = 0; mt < 2; mt++)
        #pragma unroll
        for (int nt = 0; nt < 2; nt++)
            #pragma unroll
            for (int e = 0; e < 4; e++) acc[mt][nt][e] = 0.f;

    float4 xr0, xr1, wr0, wr1;
    xr0 = *(const float4*)xg0;
    xr1 = *(const float4*)xg1;
    wr0 = *(const float4*)wg0;
    wr1 = *(const float4*)wg1;

    {
        uint4 u;
        u.x = f2tf32(xr0.x); u.y = f2tf32(xr0.y); u.z = f2tf32(xr0.z); u.w = f2tf32(xr0.w);
        *(uint4*)&Xs[0][lrow0][lcol] = u;
        u.x = f2tf32(xr1.x); u.y = f2tf32(xr1.y); u.z = f2tf32(xr1.z); u.w = f2tf32(xr1.w);
        *(uint4*)&Xs[0][lrow1][lcol] = u;
        u.x = f2tf32(wr0.x); u.y = f2tf32(wr0.y); u.z = f2tf32(wr0.z); u.w = f2tf32(wr0.w);
        *(uint4*)&Ws[0][lrow0][lcol] = u;
        u.x = f2tf32(wr1.x); u.y = f2tf32(wr1.y); u.z = f2tf32(wr1.z); u.w = f2tf32(wr1.w);
        *(uint4*)&Ws[0][lrow1][lcol] = u;
    }
    __syncthreads();

    int buf = 0;
    #pragma unroll 1
    for (int it = 0; it < KSL / 32; it++) {
        if (it < KSL / 32 - 1) {
            const int k0 = (it + 1) * 32;
            xr0 = *(const float4*)(xg0 + k0);
            xr1 = *(const float4*)(xg1 + k0);
            wr0 = *(const float4*)(wg0 + k0);
            wr1 = *(const float4*)(wg1 + k0);
        }

        #pragma unroll
        for (int ks = 0; ks < 4; ks++) {
            const int ko = ks * 8;
            uint32_t af[2][4];
            #pragma unroll
            for (int mt = 0; mt < 2; mt++) {
                const int r = warp_m * 32 + mt * 16 + g;
                af[mt][0] = Xs[buf][r][ko + tig];
                af[mt][1] = Xs[buf][r + 8][ko + tig];
                af[mt][2] = Xs[buf][r][ko + tig + 4];
                af[mt][3] = Xs[buf][r + 8][ko + tig + 4];
            }
            uint32_t bfr[2][2];
            #pragma unroll
            for (int nt = 0; nt < 2; nt++) {
                const int c = warp_n * 16 + nt * 8 + g;
                bfr[nt][0] = Ws[buf][c][ko + tig];
                bfr[nt][1] = Ws[buf][c][ko + tig + 4];
            }
            #pragma unroll
            for (int mt = 0; mt < 2; mt++)
                #pragma unroll
                for (int nt = 0; nt < 2; nt++)
                    mma_tf32(acc[mt][nt], af[mt], bfr[nt]);
        }

        if (it < KSL / 32 - 1) {
            const int nb = buf ^ 1;
            uint4 u;
            u.x = f2tf32(xr0.x); u.y = f2tf32(xr0.y); u.z = f2tf32(xr0.z); u.w = f2tf32(xr0.w);
            *(uint4*)&Xs[nb][lrow0][lcol] = u;
            u.x = f2tf32(xr1.x); u.y = f2tf32(xr1.y); u.z = f2tf32(xr1.z); u.w = f2tf32(xr1.w);
            *(uint4*)&Xs[nb][lrow1][lcol] = u;
            u.x = f2tf32(wr0.x); u.y = f2tf32(wr0.y); u.z = f2tf32(wr0.z); u.w = f2tf32(wr0.w);
            *(uint4*)&Ws[nb][lrow0][lcol] = u;
            u.x = f2tf32(wr1.x); u.y = f2tf32(wr1.y); u.z = f2tf32(wr1.z); u.w = f2tf32(wr1.w);
            *(uint4*)&Ws[nb][lrow1][lcol] = u;
            __syncthreads();
            buf = nb;
        }
    }

    // write raw partials (L2-resident)
    float* outp = g_part + (size_t)s * ((size_t)B_ * NG * M_);
    #pragma unroll
    for (int mt = 0; mt < 2; mt++) {
        const int r0 = warp_m * 32 + mt * 16 + g;
        #pragma unroll
        for (int nt = 0; nt < 2; nt++) {
            const int ncol = n_global0 + warp_n * 16 + nt * 8 + 2 * tig;
            *(float2*)&outp[(size_t)r0 * (NG * M_) + ncol] =
                make_float2(acc[mt][nt][0], acc[mt][nt][1]);
            *(float2*)&outp[(size_t)(r0 + 8) * (NG * M_) + ncol] =
                make_float2(acc[mt][nt][2], acc[mt][nt][3]);
        }
    }
}

// ---------------------------------------------------------------------------
// Kernel 1b: reduce partials + bias + activation -> g_gates[gate][b][m]
// ---------------------------------------------------------------------------
__global__ __launch_bounds__(256)
void gates_reduce(const float* __restrict__ bq, const float* __restrict__ bk,
                  const float* __restrict__ bv, const float* __restrict__ bi,
                  const float* __restrict__ bf, const float* __restrict__ bo)
{
    const int idx = blockIdx.x * 256 + threadIdx.x;   // [0, 98304)
    const int b   = idx / (NG * M_ / 4);
    const int c4  = idx % (NG * M_ / 4);
    const int n   = c4 * 4;
    const int gate = n >> 10;
    const int nl   = n & (M_ - 1);

    const float* bias;
    switch (gate) {
        case 0: bias = bq; break;
        case 1: bias = bk; break;
        case 2: bias = bv; break;
        case 3: bias = bi; break;
        case 4: bias = bf; break;
        default: bias = bo; break;
    }

    float4 acc = *(const float4*)&g_part[((size_t)0 * B_ + b) * (NG * M_) + n];
    #pragma unroll
    for (int s = 1; s < NSPLIT; s++) {
        float4 p = *(const float4*)&g_part[((size_t)s * B_ + b) * (NG * M_) + n];
        acc.x += p.x; acc.y += p.y; acc.z += p.z; acc.w += p.w;
    }
    const float4 bv4 = *(const float4*)&bias[nl];
    acc.x += bv4.x; acc.y += bv4.y; acc.z += bv4.z; acc.w += bv4.w;

    if (gate == 1) {
        acc.x *= 0.03125f; acc.y *= 0.03125f; acc.z *= 0.03125f; acc.w *= 0.03125f;
    } else if (gate == 3) {
        acc.x = __expf(acc.x); acc.y = __expf(acc.y);
        acc.z = __expf(acc.z); acc.w = __expf(acc.w);
    } else if (gate >= 4) {
        acc.x = 1.f / (1.f + __expf(-acc.x));
        acc.y = 1.f / (1.f + __expf(-acc.y));
        acc.z = 1.f / (1.f + __expf(-acc.z));
        acc.w = 1.f / (1.f + __expf(-acc.w));
    }
    *(float4*)&g_gates[(size_t)gate * (B_ * M_) + b * M_ + nl] = acc;
}

// ---------------------------------------------------------------------------
// Kernel 2 (fused, pipelined — measured 82.2us, ~93% of practical HBM ceiling):
// C_t update + h_tilde + n_t + denom + h_t.
// grid = (16, 64). Cross-row software pipeline: row r+1's 8 streaming loads
// are issued before row r's compute/store/reduce.
// ---------------------------------------------------------------------------
__global__ __launch_bounds__(256)
void update_C(const float* __restrict__ Cprev, const float* __restrict__ nprev,
              float* __restrict__ Cout, float* __restrict__ out_h,
              float* __restrict__ out_n)
{
    const int b = blockIdx.y;
    __shared__ float sk[M_];
    __shared__ float sq[M_];
    __shared__ float red[8];
    __shared__ float s_inv;

    const float* gq = g_gates + 0 * (B_ * M_) + b * M_;
    const float* gk = g_gates + 1 * (B_ * M_) + b * M_;
    ((float4*)sk)[threadIdx.x] = ((const float4*)gk)[threadIdx.x];
    ((float4*)sq)[threadIdx.x] = ((const float4*)gq)[threadIdx.x];

    const int warp = threadIdx.x >> 5;
    const int lane = threadIdx.x & 31;
    const float* gv = g_gates + 2 * (B_ * M_) + b * M_;
    const float* gi = g_gates + 3 * (B_ * M_) + b * M_;
    const float* gf = g_gates + 4 * (B_ * M_) + b * M_;
    const float* go = g_gates + 5 * (B_ * M_) + b * M_;

    __syncthreads();

    // --- denom prologue: n_t = f*n_prev + i*k ; part = n_t . q ---
    {
        const int t = threadIdx.x;
        float4 f4 = ((const float4*)gf)[t];
        float4 i4 = ((const float4*)gi)[t];
        float4 p4 = ((const float4*)(nprev + b * M_))[t];
        float4 k4 = ((const float4*)sk)[t];
        float4 q4 = ((const float4*)sq)[t];
        float4 n4;
        n4.x = fmaf(f4.x, p4.x, i4.x * k4.x);
        n4.y = fmaf(f4.y, p4.y, i4.y * k4.y);
        n4.z = fmaf(f4.z, p4.z, i4.z * k4.z);
        n4.w = fmaf(f4.w, p4.w, i4.w * k4.w);
        if (blockIdx.x == 0)
            ((float4*)(out_n + b * M_))[t] = n4;
        float part = n4.x * q4.x + n4.y * q4.y + n4.z * q4.z + n4.w * q4.w;
        #pragma unroll
        for (int off = 16; off; off >>= 1)
            part += __shfl_xor_sync(0xffffffffu, part, off);
        if (lane == 0) red[warp] = part;
        __syncthreads();
        if (threadIdx.x == 0) {
            float d = red[0] + red[1] + red[2] + red[3]
                    + red[4] + red[5] + red[6] + red[7];
            s_inv = 1.0f / fmaxf(d, 1.0f);
        }
        __syncthreads();
    }
    const float inv = s_inv;

    const float4* sk4 = (const float4*)sk;
    const float4* sq4 = (const float4*)sq;

    const int m_base = blockIdx.x * 64 + warp;

    float4 cur[8], nxt[8];
    int m = m_base;
    float fm = gf[m];
    float cm = gi[m] * gv[m];
    {
        const float4* cp = (const float4*)(Cprev + ((size_t)b * M_ + m) * M_);
        #pragma unroll
        for (int j = 0; j < 8; j++) cur[j] = __ldcs(cp + j * 32 + lane);
    }

    #pragma unroll
    for (int r = 0; r < 8; r++) {
        float fmn = 0.f, cmn = 0.f;
        if (r < 7) {
            const int mn = m_base + (r + 1) * 8;
            fmn = gf[mn];
            cmn = gi[mn] * gv[mn];
            const float4* cpn = (const float4*)(Cprev + ((size_t)b * M_ + mn) * M_);
            #pragma unroll
            for (int j = 0; j < 8; j++) nxt[j] = __ldcs(cpn + j * 32 + lane);
        }

        float4* co = (float4*)(Cout + ((size_t)b * M_ + m) * M_);
        float dot0 = 0.f, dot1 = 0.f;
        #pragma unroll
        for (int j = 0; j < 8; j++) {
            const int n4 = j * 32 + lane;
            float4 kk = sk4[n4];
            float4 qq = sq4[n4];
            float4 o;
            o.x = fmaf(fm, cur[j].x, cm * kk.x);
            o.y = fmaf(fm, cur[j].y, cm * kk.y);
            o.z = fmaf(fm, cur[j].z, cm * kk.z);
            o.w = fmaf(fm, cur[j].w, cm * kk.w);
            __stcs(co + n4, o);
            if (j & 1) {
                dot1 = fmaf(o.x, qq.x, dot1);
                dot1 = fmaf(o.y, qq.y, dot1);
                dot1 = fmaf(o.z, qq.z, dot1);
                dot1 = fmaf(o.w, qq.w, dot1);
            } else {
                dot0 = fmaf(o.x, qq.x, dot0);
                dot0 = fmaf(o.y, qq.y, dot0);
                dot0 = fmaf(o.z, qq.z, dot0);
                dot0 = fmaf(o.w, qq.w, dot0);
            }
        }
        float dot = dot0 + dot1;
        #pragma unroll
        for (int off = 16; off; off >>= 1)
            dot += __shfl_xor_sync(0xffffffffu, dot, off);
        if (lane == 0)
            out_h[b * M_ + m] = go[m] * dot * inv;

        m = m_base + (r + 1) * 8;
        fm = fmn;
        cm = cmn;
        #pragma unroll
        for (int j = 0; j < 8; j++) cur[j] = nxt[j];
    }
}

// ---------------------------------------------------------------------------
// Launch. Inputs (metadata order):
// 0 x, 1 h_prev, 2 c_prev, 3 C_prev, 4 n_prev, 5 m_prev,
// 6 Wq, 7 bq, 8 Wk, 9 bk, 10 Wv, 11 bv, 12 Wi, 13 bi, 14 Wf, 15 bf, 16 Wo, 17 bo
// Output: concat(h_t [64*1024], C_t [64*1024*1024], n_t [64*1024])
// ---------------------------------------------------------------------------
extern "C" void kernel_launch(void* const* d_in, const int* in_sizes, int n_in,
                              void* d_out, int out_size)
{
    const float* x     = (const float*)d_in[0];
    const float* Cprev = (const float*)d_in[3];
    const float* nprev = (const float*)d_in[4];

    const float* Wq = (const float*)d_in[6];  const float* bq = (const float*)d_in[7];
    const float* Wk = (const float*)d_in[8];  const float* bk = (const float*)d_in[9];
    const float* Wv = (const float*)d_in[10]; const float* bv = (const float*)d_in[11];
    const float* Wi = (const float*)d_in[12]; const float* bi = (const float*)d_in[13];
    const float* Wf = (const float*)d_in[14]; const float* bf = (const float*)d_in[15];
    const float* Wo = (const float*)d_in[16]; const float* bo = (const float*)d_in[17];

    float* out   = (float*)d_out;
    float* out_h = out;                                    // [64*1024]
    float* out_C = out + (size_t)B_ * M_;                  // [64*1024*1024]
    float* out_n = out + (size_t)B_ * M_ + (size_t)B_ * M_ * M_;

    dim3 grid1(96, NSPLIT);
    gates_mma_sk<<<grid1, 256>>>(x, Wq, Wk, Wv, Wi, Wf, Wo);

    gates_reduce<<<384, 256>>>(bq, bk, bv, bi, bf, bo);

    dim3 grid2(16, 64);
    update_C<<<grid2, 256>>>(Cprev, nprev, out_C, out_h, out_n);
}